// round 2
// baseline (speedup 1.0000x reference)
#include <cuda_runtime.h>
#include <math.h>
#include <stdint.h>

// ---------------- problem constants ----------------
#define BB    8
#define HH    56
#define WW    56
#define DIM   256
#define FFND  1024
#define NHD   8
#define KDIM  32
#define SPAT  (HH*WW)          // 3136
#define NPIX  (BB*SPAT)        // 25088
#define SCALEF 0.17677669529663687f   // 32^-0.5

// ---------------- scratch (device globals; no allocs allowed) ----------------
__device__ float g_x1  [NPIX*DIM];   // x + cpe   (shortcut 1)
__device__ float g_xn  [NPIX*DIM];   // LN output (reused for LN1 and LN2)
__device__ float g_q   [NPIX*DIM];   // roped q,  layout (B*NH, H, W, KD)
__device__ float g_k   [NPIX*DIM];   // roped+scaled k, same layout
__device__ float g_v   [NPIX*DIM];   // v, same layout
__device__ float g_lep [NPIX*DIM];   // lepe, pixel-channel layout
__device__ float g_vw  [NPIX*DIM];   // row-attention output, head layout
__device__ float g_attn[NPIX*DIM];   // col-attention output, flat == reshape
__device__ float g_x2  [NPIX*DIM];   // shortcut 2
__device__ float g_hdn [NPIX*FFND];
__device__ float g_hdn2[NPIX*FFND];
__device__ float g_sin [SPAT*KDIM];
__device__ float g_cos [SPAT*KDIM];

// ---------------- RoPE table (fp64 for accuracy, tiny) ----------------
__global__ void rope_table_kernel() {
    int i = blockIdx.x * 256 + threadIdx.x;          // SPAT*16 threads
    if (i >= SPAT * 16) return;
    int pos = i >> 4, t = i & 15;
    double ang = pow(10000.0, -(double)t / 15.0);
    double ph  = (double)pos * ang;
    float s = (float)sin(ph), c = (float)cos(ph);
    int b = pos * KDIM + 2 * t;
    g_sin[b] = s; g_sin[b + 1] = s;
    g_cos[b] = c; g_cos[b + 1] = c;
}

// ---------------- depthwise 3x3 (cpe): out = x + conv(x) + bias ----------------
__global__ __launch_bounds__(256) void cpe_kernel(const float* __restrict__ x,
                                                  const float* __restrict__ kw,
                                                  const float* __restrict__ kb,
                                                  float* __restrict__ out) {
    int idx = blockIdx.x * 256 + threadIdx.x;        // NPIX*DIM threads
    int c = idx & (DIM - 1); int pix = idx >> 8;
    int w = pix % WW; int hb = pix / WW; int h = hb % HH; int b = hb / HH;
    float acc = kb[c];
    #pragma unroll
    for (int kh = 0; kh < 3; kh++) {
        int hh = h + kh - 1; if ((unsigned)hh >= HH) continue;
        #pragma unroll
        for (int kv = 0; kv < 3; kv++) {
            int ww = w + kv - 1; if ((unsigned)ww >= WW) continue;
            acc = fmaf(x[((size_t)b * SPAT + hh * WW + ww) * DIM + c],
                       kw[(kh * 3 + kv) * DIM + c], acc);
        }
    }
    out[idx] = x[idx] + acc;
}

// ---------------- LayerNorm (one warp per pixel) ----------------
__global__ __launch_bounds__(256) void ln_kernel(const float* __restrict__ x,
                                                 const float* __restrict__ gam,
                                                 const float* __restrict__ bet,
                                                 float* __restrict__ out) {
    int warp = threadIdx.x >> 5, lane = threadIdx.x & 31;
    int pix = blockIdx.x * 8 + warp;
    const float* row = x + (size_t)pix * DIM;
    float v[8], s = 0.f, s2 = 0.f;
    #pragma unroll
    for (int u = 0; u < 8; u++) { v[u] = row[lane + u * 32]; s += v[u]; s2 += v[u] * v[u]; }
    #pragma unroll
    for (int o = 16; o; o >>= 1) {
        s  += __shfl_xor_sync(0xffffffffu, s,  o);
        s2 += __shfl_xor_sync(0xffffffffu, s2, o);
    }
    float mean = s * (1.f / DIM);
    float var  = s2 * (1.f / DIM) - mean * mean;
    float rstd = rsqrtf(var + 1e-6f);
    float* orow = out + (size_t)pix * DIM;
    #pragma unroll
    for (int u = 0; u < 8; u++) {
        int c = lane + u * 32;
        orow[c] = (v[u] - mean) * rstd * gam[c] + bet[c];
    }
}

// ---------------- generic SGEMM: C = A(NxK) * W(MxK)^T, fused epilogues ----------------
// BM=128, BN=64, BK=16, 256 threads, 8x4 per thread, reg-pipelined global loads.
#define EPI_QROPE 0
#define EPI_KROPE 1
#define EPI_VSCAT 2
#define EPI_RES   3
#define EPI_GELU  4

__device__ __forceinline__ float geluf(float x) {
    return 0.5f * x * (1.0f + erff(x * 0.70710678118654752f));
}

template<int EPI, bool DUAL>
__global__ __launch_bounds__(256, 2) void gemm_k(const float* __restrict__ A,
                                                 const float* __restrict__ A2,
                                                 const float* __restrict__ Wm,
                                                 const float* __restrict__ bias,
                                                 const float* __restrict__ res,
                                                 float* __restrict__ Cout,
                                                 int K, int M) {
    __shared__ float As[16][132];
    __shared__ float Bs[16][68];
    const int tid = threadIdx.x;
    const int tx = tid & 15, ty = tid >> 4;
    const int row0 = blockIdx.x * 128, col0 = blockIdx.y * 64;

    float acc[8][4];
    #pragma unroll
    for (int i = 0; i < 8; i++)
        #pragma unroll
        for (int j = 0; j < 4; j++) acc[i][j] = 0.f;

    const int alr = tid >> 1, alk = (tid & 1) * 8;
    const int blr = tid >> 2, blk = (tid & 3) * 4;
    const size_t aoff = (size_t)(row0 + alr) * K + alk;
    const size_t boff = (size_t)(col0 + blr) * K + blk;

    // prologue: load tile 0 into registers
    float4 a0 = *(const float4*)(A + aoff);
    float4 a1 = *(const float4*)(A + aoff + 4);
    if (DUAL) {
        float4 c0 = *(const float4*)(A2 + aoff);
        float4 c1 = *(const float4*)(A2 + aoff + 4);
        a0.x += c0.x; a0.y += c0.y; a0.z += c0.z; a0.w += c0.w;
        a1.x += c1.x; a1.y += c1.y; a1.z += c1.z; a1.w += c1.w;
    }
    float4 b0 = *(const float4*)(Wm + boff);

    for (int k0 = 0; k0 < K; k0 += 16) {
        As[alk + 0][alr] = a0.x; As[alk + 1][alr] = a0.y;
        As[alk + 2][alr] = a0.z; As[alk + 3][alr] = a0.w;
        As[alk + 4][alr] = a1.x; As[alk + 5][alr] = a1.y;
        As[alk + 6][alr] = a1.z; As[alk + 7][alr] = a1.w;
        Bs[blk + 0][blr] = b0.x; Bs[blk + 1][blr] = b0.y;
        Bs[blk + 2][blr] = b0.z; Bs[blk + 3][blr] = b0.w;
        __syncthreads();

        // prefetch next tile while computing this one
        const int kn = k0 + 16;
        if (kn < K) {
            a0 = *(const float4*)(A + aoff + kn);
            a1 = *(const float4*)(A + aoff + kn + 4);
            if (DUAL) {
                float4 c0 = *(const float4*)(A2 + aoff + kn);
                float4 c1 = *(const float4*)(A2 + aoff + kn + 4);
                a0.x += c0.x; a0.y += c0.y; a0.z += c0.z; a0.w += c0.w;
                a1.x += c1.x; a1.y += c1.y; a1.z += c1.z; a1.w += c1.w;
            }
            b0 = *(const float4*)(Wm + boff + kn);
        }

        #pragma unroll
        for (int kk = 0; kk < 16; kk++) {
            float4 av0 = *(const float4*)&As[kk][ty * 8];
            float4 av1 = *(const float4*)&As[kk][ty * 8 + 4];
            float4 bv  = *(const float4*)&Bs[kk][tx * 4];
            float ar[8] = {av0.x, av0.y, av0.z, av0.w, av1.x, av1.y, av1.z, av1.w};
            float br[4] = {bv.x, bv.y, bv.z, bv.w};
            #pragma unroll
            for (int i = 0; i < 8; i++)
                #pragma unroll
                for (int j = 0; j < 4; j++)
                    acc[i][j] = fmaf(ar[i], br[j], acc[i][j]);
        }
        __syncthreads();
    }

    #pragma unroll
    for (int i = 0; i < 8; i++) {
        const int r = row0 + ty * 8 + i;
        if (EPI == EPI_RES) {
            const int c = col0 + tx * 4;
            const float4 rv = *(const float4*)(res + (size_t)r * M + c);
            float4 o;
            o.x = acc[i][0] + bias[c + 0] + rv.x;
            o.y = acc[i][1] + bias[c + 1] + rv.y;
            o.z = acc[i][2] + bias[c + 2] + rv.z;
            o.w = acc[i][3] + bias[c + 3] + rv.w;
            *(float4*)(Cout + (size_t)r * M + c) = o;
        } else if (EPI == EPI_GELU) {
            const int c = col0 + tx * 4;
            float4 o;
            o.x = geluf(acc[i][0] + bias[c + 0]);
            o.y = geluf(acc[i][1] + bias[c + 1]);
            o.z = geluf(acc[i][2] + bias[c + 2]);
            o.w = geluf(acc[i][3] + bias[c + 3]);
            *(float4*)(Cout + (size_t)r * M + c) = o;
        } else {
            const int b = r / SPAT, sp = r - b * SPAT;
            #pragma unroll
            for (int jp = 0; jp < 4; jp += 2) {
                const int c = col0 + tx * 4 + jp;
                float v0 = acc[i][jp]     + bias[c];
                float v1 = acc[i][jp + 1] + bias[c + 1];
                const int n = c >> 5, d = c & 31;
                float* dst = Cout + (size_t)(b * NHD + n) * (SPAT * KDIM) + sp * KDIM + d;
                if (EPI == EPI_VSCAT) {
                    dst[0] = v0; dst[1] = v1;
                } else {
                    if (EPI == EPI_KROPE) { v0 *= SCALEF; v1 *= SCALEF; }
                    float s = g_sin[sp * KDIM + d], co = g_cos[sp * KDIM + d];
                    dst[0] = v0 * co - v1 * s;
                    dst[1] = v1 * co + v0 * s;
                }
            }
        }
    }
}

// ---------------- lepe: 5x5 depthwise conv of v (head layout in, pixel layout out) ----
__global__ __launch_bounds__(256) void lepe_kernel(const float* __restrict__ v,
                                                   const float* __restrict__ kw,
                                                   const float* __restrict__ kb,
                                                   float* __restrict__ out) {
    int idx = blockIdx.x * 256 + threadIdx.x;        // NPIX*DIM
    int c = idx & (DIM - 1); int pix = idx >> 8;
    int w = pix % WW; int hb = pix / WW; int h = hb % HH; int b = hb / HH;
    int n = c >> 5, d = c & 31;
    const float* vb = v + (size_t)(b * NHD + n) * (SPAT * KDIM) + d;
    float acc = kb[c];
    #pragma unroll
    for (int kh = 0; kh < 5; kh++) {
        int hh = h + kh - 2; if ((unsigned)hh >= HH) continue;
        #pragma unroll
        for (int kv = 0; kv < 5; kv++) {
            int ww = w + kv - 2; if ((unsigned)ww >= WW) continue;
            acc = fmaf(vb[(hh * WW + ww) * KDIM], kw[(kh * 5 + kv) * DIM + c], acc);
        }
    }
    out[idx] = acc;
}

// ---------------- row attention: per (b,n,h): vw = softmax(Q K^T) V ----------------
__global__ __launch_bounds__(64) void rowattn_kernel(const float* __restrict__ q,
                                                     const float* __restrict__ k,
                                                     const float* __restrict__ v,
                                                     float* __restrict__ vw) {
    int blk = blockIdx.x;                 // bn*56 + h
    int bn = blk / HH, h = blk % HH;
    const size_t base = ((size_t)bn * SPAT + h * WW) * KDIM;
    __shared__ float Ks[WW * KDIM], Vs[WW * KDIM], Ss[WW][57];
    int t = threadIdx.x;
    for (int i = t; i < WW * KDIM; i += 64) { Ks[i] = k[base + i]; Vs[i] = v[base + i]; }
    __syncthreads();
    if (t < WW) {
        float qr[KDIM];
        #pragma unroll
        for (int d = 0; d < KDIM; d++) qr[d] = q[base + t * KDIM + d];
        float mx = -1e30f;
        for (int j = 0; j < WW; j++) {
            float s = 0.f;
            #pragma unroll
            for (int d = 0; d < KDIM; d++) s = fmaf(qr[d], Ks[j * KDIM + d], s);
            Ss[t][j] = s; mx = fmaxf(mx, s);
        }
        float sum = 0.f;
        for (int j = 0; j < WW; j++) { float e = __expf(Ss[t][j] - mx); Ss[t][j] = e; sum += e; }
        float inv = 1.f / sum;
        float acc[KDIM];
        #pragma unroll
        for (int d = 0; d < KDIM; d++) acc[d] = 0.f;
        for (int j = 0; j < WW; j++) {
            float p = Ss[t][j];
            #pragma unroll
            for (int d = 0; d < KDIM; d++) acc[d] = fmaf(p, Vs[j * KDIM + d], acc[d]);
        }
        #pragma unroll
        for (int d = 0; d < KDIM; d++) vw[base + t * KDIM + d] = acc[d] * inv;
    }
}

// ---------------- column attention: per (b,n,w): out = softmax(Q K^T) vw -----------
// Output written flat in (B*NH, H, W, KD) == the reference's raw-reshape layout.
__global__ __launch_bounds__(64) void colattn_kernel(const float* __restrict__ q,
                                                     const float* __restrict__ k,
                                                     const float* __restrict__ vw,
                                                     float* __restrict__ out) {
    int blk = blockIdx.x;                 // bn*56 + w
    int bn = blk / WW, w = blk % WW;
    const size_t base = (size_t)bn * (SPAT * KDIM) + w * KDIM;   // + j*1792 + d
    __shared__ float Ks[HH * KDIM], Vs[HH * KDIM], Ss[HH][57];
    int t = threadIdx.x;
    for (int i = t; i < HH * KDIM; i += 64) {
        int j = i >> 5, d = i & 31;
        Ks[i] = k[base + (size_t)j * (WW * KDIM) + d];
        Vs[i] = vw[base + (size_t)j * (WW * KDIM) + d];
    }
    __syncthreads();
    if (t < HH) {
        float qr[KDIM];
        #pragma unroll
        for (int d = 0; d < KDIM; d++) qr[d] = q[base + (size_t)t * (WW * KDIM) + d];
        float mx = -1e30f;
        for (int j = 0; j < HH; j++) {
            float s = 0.f;
            #pragma unroll
            for (int d = 0; d < KDIM; d++) s = fmaf(qr[d], Ks[j * KDIM + d], s);
            Ss[t][j] = s; mx = fmaxf(mx, s);
        }
        float sum = 0.f;
        for (int j = 0; j < HH; j++) { float e = __expf(Ss[t][j] - mx); Ss[t][j] = e; sum += e; }
        float inv = 1.f / sum;
        float acc[KDIM];
        #pragma unroll
        for (int d = 0; d < KDIM; d++) acc[d] = 0.f;
        for (int j = 0; j < HH; j++) {
            float p = Ss[t][j];
            #pragma unroll
            for (int d = 0; d < KDIM; d++) acc[d] = fmaf(p, Vs[j * KDIM + d], acc[d]);
        }
        float* dst = out + base + (size_t)t * (WW * KDIM);
        #pragma unroll
        for (int d = 0; d < KDIM; d++) dst[d] = acc[d] * inv;
    }
}

// ---------------- FFN depthwise 3x3: out = conv(hdn)+bias + hdn ----------------
__global__ __launch_bounds__(256) void dwffn_kernel(const float* __restrict__ x,
                                                    const float* __restrict__ kw,
                                                    const float* __restrict__ kb,
                                                    float* __restrict__ out) {
    int idx = blockIdx.x * 256 + threadIdx.x;        // NPIX*FFND
    int c = idx & (FFND - 1); int pix = idx >> 10;
    int w = pix % WW; int hb = pix / WW; int h = hb % HH; int b = hb / HH;
    float acc = kb[c];
    #pragma unroll
    for (int kh = 0; kh < 3; kh++) {
        int hh = h + kh - 1; if ((unsigned)hh >= HH) continue;
        #pragma unroll
        for (int kv = 0; kv < 3; kv++) {
            int ww = w + kv - 1; if ((unsigned)ww >= WW) continue;
            acc = fmaf(x[((size_t)b * SPAT + hh * WW + ww) * FFND + c],
                       kw[(kh * 3 + kv) * FFND + c], acc);
        }
    }
    out[idx] = x[idx] + acc;
}

// ---------------- launch ----------------
extern "C" void kernel_launch(void* const* d_in, const int* in_sizes, int n_in,
                              void* d_out, int out_size) {
    (void)in_sizes; (void)n_in; (void)out_size;
    const float* x      = (const float*)d_in[0];
    const float* cpe_w  = (const float*)d_in[1];
    const float* cpe_b  = (const float*)d_in[2];
    const float* ln1_g  = (const float*)d_in[3];
    const float* ln1_b  = (const float*)d_in[4];
    const float* wq     = (const float*)d_in[5];
    const float* bq     = (const float*)d_in[6];
    const float* wk     = (const float*)d_in[7];
    const float* bk     = (const float*)d_in[8];
    const float* wv     = (const float*)d_in[9];
    const float* bv     = (const float*)d_in[10];
    const float* lepe_w = (const float*)d_in[11];
    const float* lepe_b = (const float*)d_in[12];
    const float* wo     = (const float*)d_in[13];
    const float* bo     = (const float*)d_in[14];
    const float* ln2_g  = (const float*)d_in[15];
    const float* ln2_b  = (const float*)d_in[16];
    const float* fc1_w  = (const float*)d_in[17];
    const float* fc1_b  = (const float*)d_in[18];
    const float* dw_w   = (const float*)d_in[19];
    const float* dw_b   = (const float*)d_in[20];
    const float* fc2_w  = (const float*)d_in[21];
    const float* fc2_b  = (const float*)d_in[22];
    float* outp = (float*)d_out;

    float *x1, *xn, *q, *k, *v, *lep, *vw, *attn, *x2, *hdn, *hdn2;
    cudaGetSymbolAddress((void**)&x1,   g_x1);
    cudaGetSymbolAddress((void**)&xn,   g_xn);
    cudaGetSymbolAddress((void**)&q,    g_q);
    cudaGetSymbolAddress((void**)&k,    g_k);
    cudaGetSymbolAddress((void**)&v,    g_v);
    cudaGetSymbolAddress((void**)&lep,  g_lep);
    cudaGetSymbolAddress((void**)&vw,   g_vw);
    cudaGetSymbolAddress((void**)&attn, g_attn);
    cudaGetSymbolAddress((void**)&x2,   g_x2);
    cudaGetSymbolAddress((void**)&hdn,  g_hdn);
    cudaGetSymbolAddress((void**)&hdn2, g_hdn2);

    rope_table_kernel<<<(SPAT * 16 + 255) / 256, 256>>>();
    cpe_kernel<<<NPIX * DIM / 256, 256>>>(x, cpe_w, cpe_b, x1);
    ln_kernel<<<NPIX / 8, 256>>>(x1, ln1_g, ln1_b, xn);

    dim3 gD(NPIX / 128, DIM / 64);       // 196 x 4
    gemm_k<EPI_QROPE, false><<<gD, 256>>>(xn, nullptr, wq, bq, nullptr, q, DIM, DIM);
    gemm_k<EPI_KROPE, false><<<gD, 256>>>(xn, nullptr, wk, bk, nullptr, k, DIM, DIM);
    gemm_k<EPI_VSCAT, false><<<gD, 256>>>(xn, nullptr, wv, bv, nullptr, v, DIM, DIM);

    lepe_kernel<<<NPIX * DIM / 256, 256>>>(v, lepe_w, lepe_b, lep);
    rowattn_kernel<<<BB * NHD * HH, 64>>>(q, k, v, vw);
    colattn_kernel<<<BB * NHD * WW, 64>>>(q, k, vw, attn);

    gemm_k<EPI_RES, true><<<gD, 256>>>(attn, lep, wo, bo, x1, x2, DIM, DIM);
    ln_kernel<<<NPIX / 8, 256>>>(x2, ln2_g, ln2_b, xn);

    dim3 gF(NPIX / 128, FFND / 64);      // 196 x 16
    gemm_k<EPI_GELU, false><<<gF, 256>>>(xn, nullptr, fc1_w, fc1_b, nullptr, hdn, DIM, FFND);
    dwffn_kernel<<<NPIX * FFND / 256, 256>>>(hdn, dw_w, dw_b, hdn2);
    gemm_k<EPI_RES, false><<<gD, 256>>>(hdn2, nullptr, fc2_w, fc2_b, x2, outp, FFND, DIM);
}